// round 15
// baseline (speedup 1.0000x reference)
#include <cuda_runtime.h>
#include <cuda_bf16.h>
#include <math.h>
#include <stdint.h>

// ---------------------------------------------------------------------------
// RandomProjection: out[b,o] = mean_s( cos(x[b,s,:], p[o,:]) )
//   kernel 1: blocks 0..127: x normalize+reduce -> 4 race-free partials
//             blocks 128..191: p-norms; pre-split (p*rpn) -> bf16 hi/lo
//                              (g_ph/g_pl); zero(out)
//   kernel 2: bf16 3-term tensor GEMM (m16n8k16 + ldmatrix.x4);
//             m staged (combine partials + split), p staged as pure copy;
//             red.add.v2.f32 epilogue
// ---------------------------------------------------------------------------

#define B_     32
#define S_     512
#define D_     768
#define O_     2048
#define EPS_   1e-8f

#define KSPLIT 12
#define KB     64            // k floats per gemm block
#define OTILE  32            // o rows per gemm block
#define NOT_   (O_ / OTILE)  // 64 o-tiles
#define PA     72            // bf16 smem pitch (144B rows, LDSM conflict-free)

__device__ float         g_part[4 * B_ * D_];   // x partials (race-free)
__device__ __nv_bfloat16 g_ph[O_ * D_];         // bf16 hi of p*rpn
__device__ __nv_bfloat16 g_pl[O_ * D_];         // bf16 lo

// ---- bf16 split helpers -----------------------------------------------------
__device__ __forceinline__ void bf16_split(float v, __nv_bfloat16& h, __nv_bfloat16& l) {
    h = __float2bfloat16(v);
    l = __float2bfloat16(v - __bfloat162float(h));
}
__device__ __forceinline__ uint32_t pack2(__nv_bfloat16 lo, __nv_bfloat16 hi) {
    const __nv_bfloat162 t = __halves2bfloat162(lo, hi);   // x=lo (low 16b)
    return *reinterpret_cast<const uint32_t*>(&t);
}

// ---------------------------------------------------------------------------
// Kernel 1
// ---------------------------------------------------------------------------
__global__ void __launch_bounds__(512, 1)
reduce_x_kernel(const float* __restrict__ x, const float* __restrict__ p,
                float* __restrict__ out) {
    const int warp = threadIdx.x >> 5;
    const int lane = threadIdx.x & 31;

    if (blockIdx.x >= 128) {
        const int pb = blockIdx.x - 128;       // 0..63
        // zero out-slice: 16384 float4 / 64 blocks = 256 per block
        if (threadIdx.x < 256)
            reinterpret_cast<float4*>(out)[pb * 256 + threadIdx.x] =
                make_float4(0.f, 0.f, 0.f, 0.f);
        // p rows: 32 per block, 2 per warp: norm + scale + bf16 split
        #pragma unroll
        for (int r = 0; r < 2; r++) {
            const int o = pb * 32 + warp * 2 + r;
            const float4* prow = reinterpret_cast<const float4*>(p + (size_t)o * D_);
            float4 v[6];
            float ss = 0.f;
            #pragma unroll
            for (int c = 0; c < 6; c++) {
                v[c] = prow[lane + 32 * c];
                ss += v[c].x * v[c].x + v[c].y * v[c].y
                    + v[c].z * v[c].z + v[c].w * v[c].w;
            }
            #pragma unroll
            for (int off = 16; off > 0; off >>= 1)
                ss += __shfl_xor_sync(0xFFFFFFFFu, ss, off);
            const float rp = 1.0f / fmaxf(sqrtf(ss), EPS_);

            #pragma unroll
            for (int c = 0; c < 6; c++) {
                __nv_bfloat16 h0, l0, h1, l1, h2, l2, h3, l3;
                bf16_split(v[c].x * rp, h0, l0);
                bf16_split(v[c].y * rp, h1, l1);
                bf16_split(v[c].z * rp, h2, l2);
                bf16_split(v[c].w * rp, h3, l3);
                const size_t off2 = (size_t)o * D_ + (lane + 32 * c) * 4;
                *reinterpret_cast<uint2*>(g_ph + off2) =
                    make_uint2(pack2(h0, h1), pack2(h2, h3));
                *reinterpret_cast<uint2*>(g_pl + off2) =
                    make_uint2(pack2(l0, l1), pack2(l2, l3));
            }
        }
        return;
    }

    __shared__ float4 sm[16 * 192];

    const int q = blockIdx.x & 3;
    const int b = blockIdx.x >> 2;

    const float4* base = reinterpret_cast<const float4*>(
        x + ((size_t)b * S_ + (size_t)q * 128 + (size_t)warp * 8) * D_);

    const float inv_S = 1.0f / (float)S_;

    float4 acc[6];
    #pragma unroll
    for (int c = 0; c < 6; c++) acc[c] = make_float4(0.f, 0.f, 0.f, 0.f);

    float4 v[6];
    #pragma unroll
    for (int c = 0; c < 6; c++) v[c] = base[lane + 32 * c];

    #pragma unroll
    for (int r = 0; r < 8; r++) {
        float4 vn[6];
        if (r < 7) {
            #pragma unroll
            for (int c = 0; c < 6; c++)
                vn[c] = base[(r + 1) * 192 + lane + 32 * c];
        }
        float ss = 0.f;
        #pragma unroll
        for (int c = 0; c < 6; c++)
            ss += v[c].x * v[c].x + v[c].y * v[c].y
                + v[c].z * v[c].z + v[c].w * v[c].w;
        #pragma unroll
        for (int off = 16; off > 0; off >>= 1)
            ss += __shfl_xor_sync(0xFFFFFFFFu, ss, off);

        const float scale = inv_S / fmaxf(sqrtf(ss), EPS_);
        #pragma unroll
        for (int c = 0; c < 6; c++) {
            acc[c].x += v[c].x * scale;
            acc[c].y += v[c].y * scale;
            acc[c].z += v[c].z * scale;
            acc[c].w += v[c].w * scale;
        }
        if (r < 7) {
            #pragma unroll
            for (int c = 0; c < 6; c++) v[c] = vn[c];
        }
    }

    #pragma unroll
    for (int c = 0; c < 6; c++)
        sm[warp * 192 + lane + 32 * c] = acc[c];
    __syncthreads();

    if (threadIdx.x < 192) {
        float4 s = sm[threadIdx.x];
        #pragma unroll
        for (int w = 1; w < 16; w++) {
            const float4 t = sm[w * 192 + threadIdx.x];
            s.x += t.x; s.y += t.y; s.z += t.z; s.w += t.w;
        }
        reinterpret_cast<float4*>(g_part)[((q * B_ + b) * 192) + threadIdx.x] = s;
    }
}

// ---- ldmatrix / mma ----------------------------------------------------------
__device__ __forceinline__ void ldsm_x4(uint32_t* r, uint32_t addr) {
    asm volatile("ldmatrix.sync.aligned.m8n8.x4.shared.b16 {%0,%1,%2,%3}, [%4];"
                 : "=r"(r[0]), "=r"(r[1]), "=r"(r[2]), "=r"(r[3]) : "r"(addr));
}
__device__ __forceinline__ void mma_bf16(float* d, const uint32_t* a,
                                         uint32_t b0, uint32_t b1) {
    asm volatile(
        "mma.sync.aligned.m16n8k16.row.col.f32.bf16.bf16.f32 "
        "{%0,%1,%2,%3}, {%4,%5,%6,%7}, {%8,%9}, {%0,%1,%2,%3};"
        : "+f"(d[0]), "+f"(d[1]), "+f"(d[2]), "+f"(d[3])
        : "r"(a[0]), "r"(a[1]), "r"(a[2]), "r"(a[3]), "r"(b0), "r"(b1));
}

// ---------------------------------------------------------------------------
// Kernel 2: bf16 3-term tensor GEMM.
// Grid: 768 = 64 o-tiles x 12 k-splits (5.2 blocks/SM). Block: 128 thr, 19 KB.
// Warp: M=32 (2 m16 tiles), N=8 (warp*8 in 32-o tile), KB=64 (2 k32 chunks).
// m staged: combine 4 partials + bf16 split. p staged: pure uint4 copy.
// Per k32 per warp: 8+2 ldmatrix.x4, 12 mma. Epilogue: red.add.v2.f32 x4.
// ---------------------------------------------------------------------------
__global__ void __launch_bounds__(128, 8)
gemm_kernel(float* __restrict__ out) {
    __shared__ __align__(16) __nv_bfloat16 mh[B_ * PA];
    __shared__ __align__(16) __nv_bfloat16 ml[B_ * PA];
    __shared__ __align__(16) __nv_bfloat16 ph[OTILE * PA];
    __shared__ __align__(16) __nv_bfloat16 pl[OTILE * PA];

    const int kq  = blockIdx.x % KSPLIT;
    const int ot  = blockIdx.x / KSPLIT;    // 0..63
    const int tid = threadIdx.x;
    const int k0  = kq * KB;

    // stage m: combine 4 partials, split -> hi/lo bf16, [b][k] row-major
    {
        const float4* gp = reinterpret_cast<const float4*>(g_part);
        #pragma unroll
        for (int t = 0; t < 4; t++) {
            const int i  = tid + t * 128;    // 0..511
            const int b  = i >> 4;           // 0..31
            const int kc = i & 15;           // 0..15
            const int col = kq * 16 + kc;
            float4 s = gp[(0 * B_ + b) * 192 + col];
            #pragma unroll
            for (int e = 1; e < 4; e++) {
                const float4 t4 = gp[(e * B_ + b) * 192 + col];
                s.x += t4.x; s.y += t4.y; s.z += t4.z; s.w += t4.w;
            }
            __nv_bfloat16 h0, l0, h1, l1, h2, l2, h3, l3;
            bf16_split(s.x, h0, l0); bf16_split(s.y, h1, l1);
            bf16_split(s.z, h2, l2); bf16_split(s.w, h3, l3);
            *reinterpret_cast<uint2*>(mh + b * PA + kc * 4) =
                make_uint2(pack2(h0, h1), pack2(h2, h3));
            *reinterpret_cast<uint2*>(ml + b * PA + kc * 4) =
                make_uint2(pack2(l0, l1), pack2(l2, l3));
        }
    }
    // stage p: pure copy of pre-split bf16 (32 rows x 8 uint4 per buffer)
    #pragma unroll
    for (int t = 0; t < 2; t++) {
        const int i   = tid + t * 128;       // 0..255
        const int o   = i >> 3;              // 0..31
        const int kc8 = i & 7;               // 0..7  (8 bf16 each)
        const size_t src = (size_t)(ot * OTILE + o) * D_ + k0 + kc8 * 8;
        *reinterpret_cast<uint4*>(ph + o * PA + kc8 * 8) =
            *reinterpret_cast<const uint4*>(g_ph + src);
        *reinterpret_cast<uint4*>(pl + o * PA + kc8 * 8) =
            *reinterpret_cast<const uint4*>(g_pl + src);
    }
    __syncthreads();

    const int warp = tid >> 5;
    const int lane = tid & 31;
    const int g    = lane >> 2;          // groupID 0..7
    const int tg   = lane & 3;           // threadID_in_group 0..3

    const int arow  = (lane & 7) + ((lane >> 3) & 1) * 8;   // + mt*16
    const int akseg = (lane >> 4) & 1;                      // * 8 elements
    const int brow  = warp * 8 + (lane & 7);                // N=8 rows
    const int bko   = (lane >> 3) * 8;                      // k-seg 0,8,16,24

    const uint32_t mh_u = (uint32_t)__cvta_generic_to_shared(mh);
    const uint32_t ml_u = (uint32_t)__cvta_generic_to_shared(ml);
    const uint32_t ph_u = (uint32_t)__cvta_generic_to_shared(ph);
    const uint32_t pl_u = (uint32_t)__cvta_generic_to_shared(pl);

    float d[2][4];
    #pragma unroll
    for (int mt = 0; mt < 2; mt++)
        #pragma unroll
        for (int r = 0; r < 4; r++) d[mt][r] = 0.f;

    #pragma unroll
    for (int ks = 0; ks < 2; ks++) {
        const int kb = ks * 32;

        // B fragments for the whole k32: x4 = 4 k-segments of 8
        uint32_t bh[4], bl[4];
        {
            const uint32_t off = (brow * PA + kb + bko) * 2;
            ldsm_x4(bh, ph_u + off);
            ldsm_x4(bl, pl_u + off);
        }

        #pragma unroll
        for (int half = 0; half < 2; half++) {
            const int kb16 = kb + half * 16;
            uint32_t ah[2][4], al[2][4];
            #pragma unroll
            for (int mt = 0; mt < 2; mt++) {
                const uint32_t off =
                    ((mt * 16 + arow) * PA + kb16 + akseg * 8) * 2;
                ldsm_x4(ah[mt], mh_u + off);
                ldsm_x4(al[mt], ml_u + off);
            }
            const uint32_t b0h = bh[2 * half], b1h = bh[2 * half + 1];
            const uint32_t b0l = bl[2 * half], b1l = bl[2 * half + 1];
            #pragma unroll
            for (int mt = 0; mt < 2; mt++) {
                mma_bf16(d[mt], ah[mt], b0h, b1h);   // hi*hi
                mma_bf16(d[mt], ah[mt], b0l, b1l);   // hi*lo
                mma_bf16(d[mt], al[mt], b0h, b1h);   // lo*hi
            }
        }
    }

    // epilogue: c0,c1 = [g][2tg,2tg+1]; c2,c3 = [g+8][same]
    const int col = ot * OTILE + warp * 8 + 2 * tg;
    #pragma unroll
    for (int mt = 0; mt < 2; mt++) {
        const int row = mt * 16 + g;
        float* dst0 = out + (size_t)row * O_ + col;
        float* dst1 = out + (size_t)(row + 8) * O_ + col;
        asm volatile("red.global.add.v2.f32 [%0], {%1, %2};"
                     :: "l"(dst0), "f"(d[mt][0]), "f"(d[mt][1]) : "memory");
        asm volatile("red.global.add.v2.f32 [%0], {%1, %2};"
                     :: "l"(dst1), "f"(d[mt][2]), "f"(d[mt][3]) : "memory");
    }
}

// ---------------------------------------------------------------------------
extern "C" void kernel_launch(void* const* d_in, const int* in_sizes, int n_in,
                              void* d_out, int out_size) {
    const float* x = (const float*)d_in[0];   // [32, 512, 768]
    const float* p = (const float*)d_in[1];   // [2048, 768]
    float*     out = (float*)d_out;           // [32, 2048]

    (void)in_sizes; (void)n_in; (void)out_size;

    reduce_x_kernel<<<128 + 64, 512>>>(x, p, out);
    gemm_kernel<<<NOT_ * KSPLIT, 128>>>(out);
}

// round 16
// speedup vs baseline: 1.0114x; 1.0114x over previous
#include <cuda_runtime.h>
#include <cuda_bf16.h>
#include <math.h>
#include <stdint.h>

// ---------------------------------------------------------------------------
// RandomProjection: out[b,o] = mean_s( cos(x[b,s,:], p[o,:]) )
//   kernel 1: blocks 0..127: x normalize+reduce -> partials; ticket winner
//             combines + splits m -> bf16 g_mh/g_ml.
//             blocks 128..191: p-norms; pre-split (p*rpn) -> g_ph/g_pl;
//             zero(out).
//   kernel 2: bf16 3-term tensor GEMM; staging = pure uint4 copies;
//             red.add.v2.f32 epilogue.
// ---------------------------------------------------------------------------

#define B_     32
#define S_     512
#define D_     768
#define O_     2048
#define EPS_   1e-8f

#define KSPLIT 12
#define KB     64            // k floats per gemm block
#define OTILE  32            // o rows per gemm block
#define NOT_   (O_ / OTILE)  // 64 o-tiles
#define PA     72            // bf16 smem pitch (144B rows, LDSM conflict-free)

__device__ float         g_part[4 * B_ * D_];   // x partials (race-free)
__device__ __nv_bfloat16 g_mh[B_ * D_];         // bf16 hi of m
__device__ __nv_bfloat16 g_ml[B_ * D_];         // bf16 lo
__device__ __nv_bfloat16 g_ph[O_ * D_];         // bf16 hi of p*rpn
__device__ __nv_bfloat16 g_pl[O_ * D_];         // bf16 lo
__device__ int           g_ticket[B_];          // zero-init, self-reset

// ---- bf16 split helpers -----------------------------------------------------
__device__ __forceinline__ void bf16_split(float v, __nv_bfloat16& h, __nv_bfloat16& l) {
    h = __float2bfloat16(v);
    l = __float2bfloat16(v - __bfloat162float(h));
}
__device__ __forceinline__ uint32_t pack2(__nv_bfloat16 lo, __nv_bfloat16 hi) {
    const __nv_bfloat162 t = __halves2bfloat162(lo, hi);   // x=lo (low 16b)
    return *reinterpret_cast<const uint32_t*>(&t);
}

// ---------------------------------------------------------------------------
// Kernel 1
// ---------------------------------------------------------------------------
__global__ void __launch_bounds__(512, 1)
reduce_x_kernel(const float* __restrict__ x, const float* __restrict__ p,
                float* __restrict__ out) {
    const int warp = threadIdx.x >> 5;
    const int lane = threadIdx.x & 31;

    if (blockIdx.x >= 128) {
        const int pb = blockIdx.x - 128;       // 0..63
        if (threadIdx.x < 256)
            reinterpret_cast<float4*>(out)[pb * 256 + threadIdx.x] =
                make_float4(0.f, 0.f, 0.f, 0.f);
        // p rows: 32 per block, 2 per warp: norm + scale + bf16 split
        #pragma unroll
        for (int r = 0; r < 2; r++) {
            const int o = pb * 32 + warp * 2 + r;
            const float4* prow = reinterpret_cast<const float4*>(p + (size_t)o * D_);
            float4 v[6];
            float ss = 0.f;
            #pragma unroll
            for (int c = 0; c < 6; c++) {
                v[c] = prow[lane + 32 * c];
                ss += v[c].x * v[c].x + v[c].y * v[c].y
                    + v[c].z * v[c].z + v[c].w * v[c].w;
            }
            #pragma unroll
            for (int off = 16; off > 0; off >>= 1)
                ss += __shfl_xor_sync(0xFFFFFFFFu, ss, off);
            const float rp = 1.0f / fmaxf(sqrtf(ss), EPS_);

            #pragma unroll
            for (int c = 0; c < 6; c++) {
                __nv_bfloat16 h0, l0, h1, l1, h2, l2, h3, l3;
                bf16_split(v[c].x * rp, h0, l0);
                bf16_split(v[c].y * rp, h1, l1);
                bf16_split(v[c].z * rp, h2, l2);
                bf16_split(v[c].w * rp, h3, l3);
                const size_t off2 = (size_t)o * D_ + (lane + 32 * c) * 4;
                *reinterpret_cast<uint2*>(g_ph + off2) =
                    make_uint2(pack2(h0, h1), pack2(h2, h3));
                *reinterpret_cast<uint2*>(g_pl + off2) =
                    make_uint2(pack2(l0, l1), pack2(l2, l3));
            }
        }
        return;
    }

    __shared__ float4 sm[16 * 192];
    __shared__ int is_last;

    const int q = blockIdx.x & 3;
    const int b = blockIdx.x >> 2;

    const float4* base = reinterpret_cast<const float4*>(
        x + ((size_t)b * S_ + (size_t)q * 128 + (size_t)warp * 8) * D_);

    const float inv_S = 1.0f / (float)S_;

    float4 acc[6];
    #pragma unroll
    for (int c = 0; c < 6; c++) acc[c] = make_float4(0.f, 0.f, 0.f, 0.f);

    float4 v[6];
    #pragma unroll
    for (int c = 0; c < 6; c++) v[c] = base[lane + 32 * c];

    #pragma unroll
    for (int r = 0; r < 8; r++) {
        float4 vn[6];
        if (r < 7) {
            #pragma unroll
            for (int c = 0; c < 6; c++)
                vn[c] = base[(r + 1) * 192 + lane + 32 * c];
        }
        float ss = 0.f;
        #pragma unroll
        for (int c = 0; c < 6; c++)
            ss += v[c].x * v[c].x + v[c].y * v[c].y
                + v[c].z * v[c].z + v[c].w * v[c].w;
        #pragma unroll
        for (int off = 16; off > 0; off >>= 1)
            ss += __shfl_xor_sync(0xFFFFFFFFu, ss, off);

        const float scale = inv_S / fmaxf(sqrtf(ss), EPS_);
        #pragma unroll
        for (int c = 0; c < 6; c++) {
            acc[c].x += v[c].x * scale;
            acc[c].y += v[c].y * scale;
            acc[c].z += v[c].z * scale;
            acc[c].w += v[c].w * scale;
        }
        if (r < 7) {
            #pragma unroll
            for (int c = 0; c < 6; c++) v[c] = vn[c];
        }
    }

    #pragma unroll
    for (int c = 0; c < 6; c++)
        sm[warp * 192 + lane + 32 * c] = acc[c];
    __syncthreads();

    if (threadIdx.x < 192) {
        float4 s = sm[threadIdx.x];
        #pragma unroll
        for (int w = 1; w < 16; w++) {
            const float4 t = sm[w * 192 + threadIdx.x];
            s.x += t.x; s.y += t.y; s.z += t.z; s.w += t.w;
        }
        reinterpret_cast<float4*>(g_part)[((q * B_ + b) * 192) + threadIdx.x] = s;
    }

    // ticket: last of 4 blocks for this b combines partials -> bf16 split m
    __threadfence();
    __syncthreads();
    if (threadIdx.x == 0)
        is_last = (atomicAdd(&g_ticket[b], 1) == 3) ? 1 : 0;
    __syncthreads();

    if (is_last) {
        __threadfence();
        if (threadIdx.x < 192) {
            const float4* gp = reinterpret_cast<const float4*>(g_part);
            float4 a  = gp[(0 * B_ + b) * 192 + threadIdx.x];
            const float4 b4 = gp[(1 * B_ + b) * 192 + threadIdx.x];
            const float4 c4 = gp[(2 * B_ + b) * 192 + threadIdx.x];
            const float4 d4 = gp[(3 * B_ + b) * 192 + threadIdx.x];
            a.x += b4.x + c4.x + d4.x;
            a.y += b4.y + c4.y + d4.y;
            a.z += b4.z + c4.z + d4.z;
            a.w += b4.w + c4.w + d4.w;
            __nv_bfloat16 h0, l0, h1, l1, h2, l2, h3, l3;
            bf16_split(a.x, h0, l0); bf16_split(a.y, h1, l1);
            bf16_split(a.z, h2, l2); bf16_split(a.w, h3, l3);
            const size_t off2 = (size_t)b * D_ + threadIdx.x * 4;
            *reinterpret_cast<uint2*>(g_mh + off2) =
                make_uint2(pack2(h0, h1), pack2(h2, h3));
            *reinterpret_cast<uint2*>(g_ml + off2) =
                make_uint2(pack2(l0, l1), pack2(l2, l3));
        }
        if (threadIdx.x == 0) g_ticket[b] = 0;
    }
}

// ---- ldmatrix / mma ----------------------------------------------------------
__device__ __forceinline__ void ldsm_x4(uint32_t* r, uint32_t addr) {
    asm volatile("ldmatrix.sync.aligned.m8n8.x4.shared.b16 {%0,%1,%2,%3}, [%4];"
                 : "=r"(r[0]), "=r"(r[1]), "=r"(r[2]), "=r"(r[3]) : "r"(addr));
}
__device__ __forceinline__ void mma_bf16(float* d, const uint32_t* a,
                                         uint32_t b0, uint32_t b1) {
    asm volatile(
        "mma.sync.aligned.m16n8k16.row.col.f32.bf16.bf16.f32 "
        "{%0,%1,%2,%3}, {%4,%5,%6,%7}, {%8,%9}, {%0,%1,%2,%3};"
        : "+f"(d[0]), "+f"(d[1]), "+f"(d[2]), "+f"(d[3])
        : "r"(a[0]), "r"(a[1]), "r"(a[2]), "r"(a[3]), "r"(b0), "r"(b1));
}

// ---------------------------------------------------------------------------
// Kernel 2: bf16 3-term tensor GEMM, pure-copy staging.
// Grid: 768 = 64 o-tiles x 12 k-splits. Block: 128 thr, 18 KB smem.
// Warp: M=32 (2 m16 tiles), N=8 (warp*8 in 32-o tile), KB=64.
// ---------------------------------------------------------------------------
__global__ void __launch_bounds__(128, 8)
gemm_kernel(float* __restrict__ out) {
    __shared__ __align__(16) __nv_bfloat16 mh[B_ * PA];
    __shared__ __align__(16) __nv_bfloat16 ml[B_ * PA];
    __shared__ __align__(16) __nv_bfloat16 ph[OTILE * PA];
    __shared__ __align__(16) __nv_bfloat16 pl[OTILE * PA];

    const int kq  = blockIdx.x % KSPLIT;
    const int ot  = blockIdx.x / KSPLIT;    // 0..63
    const int tid = threadIdx.x;
    const int k0  = kq * KB;

    // stage m: pure uint4 copy of pre-split bf16 (32 rows x 8 uint4 x 2 bufs)
    #pragma unroll
    for (int t = 0; t < 4; t++) {
        const int i   = tid + t * 128;       // 0..511
        const int sel = i >> 8;              // 0: hi, 1: lo
        const int j   = i & 255;
        const int b   = j >> 3;              // 0..31
        const int kc8 = j & 7;               // 0..7
        const size_t src = (size_t)b * D_ + k0 + kc8 * 8;
        const __nv_bfloat16* g = sel ? g_ml : g_mh;
        __nv_bfloat16* dst     = sel ? ml : mh;
        *reinterpret_cast<uint4*>(dst + b * PA + kc8 * 8) =
            *reinterpret_cast<const uint4*>(g + src);
    }
    // stage p: pure uint4 copy (32 rows x 8 uint4 x 2 bufs)
    #pragma unroll
    for (int t = 0; t < 2; t++) {
        const int i   = tid + t * 128;       // 0..255
        const int o   = i >> 3;              // 0..31
        const int kc8 = i & 7;               // 0..7
        const size_t src = (size_t)(ot * OTILE + o) * D_ + k0 + kc8 * 8;
        *reinterpret_cast<uint4*>(ph + o * PA + kc8 * 8) =
            *reinterpret_cast<const uint4*>(g_ph + src);
        *reinterpret_cast<uint4*>(pl + o * PA + kc8 * 8) =
            *reinterpret_cast<const uint4*>(g_pl + src);
    }
    __syncthreads();

    const int warp = tid >> 5;
    const int lane = tid & 31;
    const int g    = lane >> 2;          // groupID 0..7
    const int tg   = lane & 3;           // threadID_in_group 0..3

    const int arow  = (lane & 7) + ((lane >> 3) & 1) * 8;   // + mt*16
    const int akseg = (lane >> 4) & 1;                      // * 8 elements
    const int brow  = warp * 8 + (lane & 7);                // N=8 rows
    const int bko   = (lane >> 3) * 8;                      // k-seg 0,8,16,24

    const uint32_t mh_u = (uint32_t)__cvta_generic_to_shared(mh);
    const uint32_t ml_u = (uint32_t)__cvta_generic_to_shared(ml);
    const uint32_t ph_u = (uint32_t)__cvta_generic_to_shared(ph);
    const uint32_t pl_u = (uint32_t)__cvta_generic_to_shared(pl);

    float d[2][4];
    #pragma unroll
    for (int mt = 0; mt < 2; mt++)
        #pragma unroll
        for (int r = 0; r < 4; r++) d[mt][r] = 0.f;

    #pragma unroll
    for (int ks = 0; ks < 2; ks++) {
        const int kb = ks * 32;

        uint32_t bh[4], bl[4];
        {
            const uint32_t off = (brow * PA + kb + bko) * 2;
            ldsm_x4(bh, ph_u + off);
            ldsm_x4(bl, pl_u + off);
        }

        #pragma unroll
        for (int half = 0; half < 2; half++) {
            const int kb16 = kb + half * 16;
            uint32_t ah[2][4], al[2][4];
            #pragma unroll
            for (int mt = 0; mt < 2; mt++) {
                const uint32_t off =
                    ((mt * 16 + arow) * PA + kb16 + akseg * 8) * 2;
                ldsm_x4(ah[mt], mh_u + off);
                ldsm_x4(al[mt], ml_u + off);
            }
            const uint32_t b0h = bh[2 * half], b1h = bh[2 * half + 1];
            const uint32_t b0l = bl[2 * half], b1l = bl[2 * half + 1];
            #pragma unroll
            for (int mt = 0; mt < 2; mt++) {
                mma_bf16(d[mt], ah[mt], b0h, b1h);   // hi*hi
                mma_bf16(d[mt], ah[mt], b0l, b1l);   // hi*lo
                mma_bf16(d[mt], al[mt], b0h, b1h);   // lo*hi
            }
        }
    }

    // epilogue
    const int col = ot * OTILE + warp * 8 + 2 * tg;
    #pragma unroll
    for (int mt = 0; mt < 2; mt++) {
        const int row = mt * 16 + g;
        float* dst0 = out + (size_t)row * O_ + col;
        float* dst1 = out + (size_t)(row + 8) * O_ + col;
        asm volatile("red.global.add.v2.f32 [%0], {%1, %2};"
                     :: "l"(dst0), "f"(d[mt][0]), "f"(d[mt][1]) : "memory");
        asm volatile("red.global.add.v2.f32 [%0], {%1, %2};"
                     :: "l"(dst1), "f"(d[mt][2]), "f"(d[mt][3]) : "memory");
    }
}

// ---------------------------------------------------------------------------
extern "C" void kernel_launch(void* const* d_in, const int* in_sizes, int n_in,
                              void* d_out, int out_size) {
    const float* x = (const float*)d_in[0];   // [32, 512, 768]
    const float* p = (const float*)d_in[1];   // [2048, 768]
    float*     out = (float*)d_out;           // [32, 2048]

    (void)in_sizes; (void)n_in; (void)out_size;

    reduce_x_kernel<<<128 + 64, 512>>>(x, p, out);
    gemm_kernel<<<NOT_ * KSPLIT, 128>>>(out);
}